// round 7
// baseline (speedup 1.0000x reference)
#include <cuda_runtime.h>

#define BN_EPS 1e-5f
#define MAX_E 1000000

// ---- device scratch (allocation-free: __device__ globals) ----
static __device__ float g_h[(size_t)MAX_E * 64];   // h1 / h2 scratch [E,64] (256 MB)
static __device__ float g_Wt1[64 * 256];           // W1 transposed [feature][k]
static __device__ float g_Wt2[64 * 64];            // folded+transposed W2'
static __device__ float g_Wt3[64 * 64];            // folded+transposed W3'
static __device__ float g_bf2[64];                 // folded b2'
static __device__ float g_bf3[64];                 // folded b3'
static __device__ float g_sum[3][64];              // per-layer feature sums
static __device__ float g_sq[3][64];               // per-layer feature sum-of-squares
static __device__ float g_s3[64];                  // final BN scale
static __device__ float g_t3[64];                  // final BN shift
static __device__ int   g_is64;                    // batch dtype flag (1 = int64)

// ---- packed fp32x2 FMA (Blackwell FFMA2) ----
__device__ __forceinline__ void ffma2(unsigned long long& d, unsigned long long a,
                                      unsigned long long b) {
    asm("fma.rn.f32x2 %0, %1, %2, %0;" : "+l"(d) : "l"(a), "l"(b));
}
__device__ __forceinline__ float2 unpack_f32x2(unsigned long long v) {
    float2 r;
    asm("mov.b64 {%0, %1}, %2;" : "=f"(r.x), "=f"(r.y) : "l"(v));
    return r;
}

// ---- prep: zero stats, detect batch dtype, transpose W1 into g_Wt1 ----
__global__ void prep_kernel(const float* __restrict__ W1, const void* __restrict__ batch,
                            int E, int G) {
    if (blockIdx.x == 0) {
        float* s = &g_sum[0][0];
        float* q = &g_sq[0][0];
        for (int i = threadIdx.x; i < 192; i += blockDim.x) { s[i] = 0.f; q[i] = 0.f; }
        if (threadIdx.x == 0) {
            // If the buffer really holds int64 indices, every value is in [0, G).
            // If it holds int32, the int64 view packs two words and exceeds G
            // unless every odd word is zero (prob ~2^-640 over 64 samples).
            const long long* b64 = (const long long*)batch;
            int n = (E < 64) ? E : 64;   // reads n*8 <= 512 B, safe for either dtype
            int ok = 1;
            for (int i = 0; i < n; i++) {
                long long v = b64[i];
                if (v < 0 || v >= (long long)G) { ok = 0; break; }
            }
            g_is64 = ok;
        }
    }
    int tid = blockIdx.x * blockDim.x + threadIdx.x;
    for (int i = tid; i < 64 * 256; i += gridDim.x * blockDim.x) {
        int j = i >> 8, k = i & 255;
        g_Wt1[i] = W1[k * 64 + j];   // g_Wt1[j][k] = W1[k][j]
    }
}

// ---- fold BN(layer LAYER) into next layer's weights ----
template <int LAYER>
__global__ void fold_kernel(const float* __restrict__ Wn, const float* __restrict__ bn,
                            const float* __restrict__ gamma, const float* __restrict__ beta,
                            float Einv) {
    __shared__ float s[64], t[64];
    int j = threadIdx.x;  // 64 threads
    float mean = g_sum[LAYER][j] * Einv;
    float var  = g_sq[LAYER][j] * Einv - mean * mean;
    float sc = gamma[j] / sqrtf(var + BN_EPS);
    s[j] = sc;
    t[j] = beta[j] - mean * sc;
    __syncthreads();
    float* WtOut = (LAYER == 0) ? g_Wt2 : g_Wt3;
    float* bOut  = (LAYER == 0) ? g_bf2 : g_bf3;
    float bacc = bn[j];
#pragma unroll
    for (int k = 0; k < 64; k++) {
        float w = Wn[k * 64 + j];
        WtOut[j * 64 + k] = w * s[k];  // transposed + scaled
        bacc += t[k] * w;
    }
    bOut[j] = bacc;
}

// ---- finalize layer-3 BN affine params ----
__global__ void fin_kernel(const float* __restrict__ gamma, const float* __restrict__ beta,
                           float Einv) {
    int j = threadIdx.x;  // 64 threads
    float mean = g_sum[2][j] * Einv;
    float var  = g_sq[2][j] * Einv - mean * mean;
    float sc = gamma[j] / sqrtf(var + BN_EPS);
    g_s3[j] = sc;
    g_t3[j] = beta[j] - mean * sc;
}

// ---- final elementwise BN affine on d_out (in place) ----
__global__ void affine_kernel(float* __restrict__ out, int n4) {
    __shared__ float s[64], t[64];
    if (threadIdx.x < 64) { s[threadIdx.x] = g_s3[threadIdx.x]; t[threadIdx.x] = g_t3[threadIdx.x]; }
    __syncthreads();
    float4* o4 = reinterpret_cast<float4*>(out);
    for (int i = blockIdx.x * blockDim.x + threadIdx.x; i < n4; i += gridDim.x * blockDim.x) {
        float4 v = o4[i];
        int fb = (i & 15) << 2;
        v.x = v.x * s[fb] + t[fb];
        v.y = v.y * s[fb + 1] + t[fb + 1];
        v.z = v.z * s[fb + 2] + t[fb + 2];
        v.w = v.w * s[fb + 3] + t[fb + 3];
        o4[i] = v;
    }
}

// ---- fused GEMM + relu + stats kernel (all 3 layers) ----
// Block: 256 threads, tile = 128 edges x 64 features. Thread tile 8x4.
// A kept e-major in smem (conflict-free stores, no transpose). W pre-transposed.
// Inner product via f32x2: lanes carry even/odd k partial sums.
template <int KDIM, int LAYER>
__global__ void layer_kernel(const float* __restrict__ in0, const float* __restrict__ in1,
                             const float* __restrict__ in2, const float* __restrict__ ga,
                             const void* __restrict__ batch,
                             const float* __restrict__ bias1,
                             float* __restrict__ outParam, int E, int G) {
    constexpr int KP = KDIM + 4;           // pitch (floats), 16B-aligned, bank-staggered
    constexpr bool CONCAT = (LAYER == 0);
    extern __shared__ float smem[];
    float* As = smem;                       // [128][KP]
    float* Ws = smem + 128 * KP;            // [64][KP]
    __shared__ float bs[64], ssum[64], ssq[64];
    __shared__ int bIdx[128];

    const float* Wt   = (LAYER == 0) ? g_Wt1 : (LAYER == 1) ? g_Wt2 : g_Wt3;
    const float* bias = (LAYER == 0) ? bias1 : (LAYER == 1) ? g_bf2 : g_bf3;
    float* outp = (LAYER == 2) ? outParam : g_h;

    int tid = threadIdx.x;
    int eBase = blockIdx.x * 128;

    if (tid < 64) { bs[tid] = bias[tid]; ssum[tid] = 0.f; ssq[tid] = 0.f; }
    if (CONCAT) {
        if (tid < 128) {
            int ge = eBase + tid;
            int b = 0;
            if (ge < E) {
                b = g_is64 ? (int)((const long long*)batch)[ge]
                           : ((const int*)batch)[ge];
                // crash insurance; detection guarantees correctness
                b = (b < 0) ? 0 : (b >= G ? G - 1 : b);
            }
            bIdx[tid] = b;
        }
    }
    // load (already transposed) weights, coalesced read, conflict-free store
    for (int i = tid; i < 64 * KDIM; i += 256) {
        int j = i / KDIM, k = i - j * KDIM;
        Ws[j * KP + k] = Wt[i];
    }
    __syncthreads();

    // ---- stage A tile (e-major, coalesced) ----
    if (CONCAT) {
        for (int i = tid; i < 128 * 64; i += 256) {
            int e = i >> 6, f = i & 63;
            int ge = eBase + e;
            bool ok = ge < E;
            size_t off = (size_t)ge * 64 + f;
            float* row = &As[e * KP];
            row[f]       = ok ? in0[off] : 0.f;                           // src
            row[64 + f]  = ok ? in1[off] : 0.f;                           // dest
            row[128 + f] = ok ? in2[off] : 0.f;                           // edge_attr
            row[192 + f] = ok ? ga[(size_t)bIdx[e] * 64 + f] : 0.f;       // global gather
        }
    } else {
        for (int i = tid; i < 128 * 64; i += 256) {
            int e = i >> 6, f = i & 63;
            int ge = eBase + e;
            As[e * KP + f] = (ge < E) ? g_h[(size_t)ge * 64 + f] : 0.f;
        }
    }
    __syncthreads();

    // ---- register-tiled GEMM, f32x2 even/odd-k accumulation ----
    int tc = tid & 15;        // feature group: f = tc + 16j, j=0..3
    int tr = tid >> 4;        // edge group:    e = tr + 16i, i=0..7
    unsigned long long acc[8][4];
#pragma unroll
    for (int i = 0; i < 8; i++)
#pragma unroll
        for (int j = 0; j < 4; j++) acc[i][j] = 0ull;

#pragma unroll 2
    for (int kk = 0; kk < KDIM; kk += 4) {
        ulonglong2 a[8], w[4];
#pragma unroll
        for (int i = 0; i < 8; i++)
            a[i] = *reinterpret_cast<const ulonglong2*>(&As[(tr + 16 * i) * KP + kk]);
#pragma unroll
        for (int j = 0; j < 4; j++)
            w[j] = *reinterpret_cast<const ulonglong2*>(&Ws[(tc + 16 * j) * KP + kk]);
#pragma unroll
        for (int i = 0; i < 8; i++)
#pragma unroll
            for (int j = 0; j < 4; j++) {
                ffma2(acc[i][j], a[i].x, w[j].x);   // k, k+1
                ffma2(acc[i][j], a[i].y, w[j].y);   // k+2, k+3
            }
    }

    // ---- epilogue: bias + relu, store, per-feature stats ----
    float ls[4] = {0.f, 0.f, 0.f, 0.f};
    float lq[4] = {0.f, 0.f, 0.f, 0.f};
#pragma unroll
    for (int i = 0; i < 8; i++) {
        int ge = eBase + tr + 16 * i;
        bool ok = ge < E;
#pragma unroll
        for (int j = 0; j < 4; j++) {
            int f = tc + 16 * j;
            float2 p = unpack_f32x2(acc[i][j]);
            float v = fmaxf(p.x + p.y + bs[f], 0.f);
            if (ok) {
                outp[(size_t)ge * 64 + f] = v;
                ls[j] += v;
                lq[j] += v * v;
            }
        }
    }
    // reduce the two threads sharing each feature column within a warp
#pragma unroll
    for (int j = 0; j < 4; j++) {
        ls[j] += __shfl_down_sync(0xffffffffu, ls[j], 16);
        lq[j] += __shfl_down_sync(0xffffffffu, lq[j], 16);
    }
    if ((tid & 16) == 0) {
#pragma unroll
        for (int j = 0; j < 4; j++) {
            int f = tc + 16 * j;
            atomicAdd(&ssum[f], ls[j]);
            atomicAdd(&ssq[f], lq[j]);
        }
    }
    __syncthreads();
    if (tid < 64) {
        atomicAdd(&g_sum[LAYER][tid], ssum[tid]);
        atomicAdd(&g_sq[LAYER][tid], ssq[tid]);
    }
}

extern "C" void kernel_launch(void* const* d_in, const int* in_sizes, int n_in,
                              void* d_out, int out_size) {
    const float* src   = (const float*)d_in[0];
    const float* dst   = (const float*)d_in[1];
    const float* eat   = (const float*)d_in[2];
    const float* gat   = (const float*)d_in[3];
    const void*  batch = d_in[4];
    const float* W1 = (const float*)d_in[5];
    const float* b1 = (const float*)d_in[6];
    const float* W2 = (const float*)d_in[7];
    const float* b2 = (const float*)d_in[8];
    const float* W3 = (const float*)d_in[9];
    const float* b3 = (const float*)d_in[10];
    const float* g1 = (const float*)d_in[11];
    const float* be1 = (const float*)d_in[12];
    const float* g2 = (const float*)d_in[13];
    const float* be2 = (const float*)d_in[14];
    const float* g3 = (const float*)d_in[15];
    const float* be3 = (const float*)d_in[16];

    int E = in_sizes[0] / 64;
    int G = in_sizes[3] / 64;
    int nb = (E + 127) / 128;
    float Einv = 1.0f / (float)E;
    float* out = (float*)d_out;

    constexpr int SM1 = (128 + 64) * (256 + 4) * 4;  // 199,680 B
    constexpr int SMN = (128 + 64) * (64 + 4) * 4;   // 52,224 B
    cudaFuncSetAttribute(layer_kernel<256, 0>, cudaFuncAttributeMaxDynamicSharedMemorySize, SM1);
    cudaFuncSetAttribute(layer_kernel<64, 1>,  cudaFuncAttributeMaxDynamicSharedMemorySize, SMN);
    cudaFuncSetAttribute(layer_kernel<64, 2>,  cudaFuncAttributeMaxDynamicSharedMemorySize, SMN);

    prep_kernel<<<16, 256>>>(W1, batch, E, G);

    // layer 1: concat(src,dest,edge,global[batch]) @ W1 + b1 -> relu -> g_h, stats[0]
    layer_kernel<256, 0><<<nb, 256, SM1>>>(src, dst, eat, gat, batch, b1, out, E, G);
    fold_kernel<0><<<1, 64>>>(W2, b2, g1, be1, Einv);

    // layer 2: g_h @ W2' + b2' -> relu -> g_h (in place), stats[1]
    layer_kernel<64, 1><<<nb, 256, SMN>>>(src, dst, eat, gat, batch, b1, out, E, G);
    fold_kernel<1><<<1, 64>>>(W3, b3, g2, be2, Einv);

    // layer 3: g_h @ W3' + b3' -> relu -> d_out (pre-BN), stats[2]
    layer_kernel<64, 2><<<nb, 256, SMN>>>(src, dst, eat, gat, batch, b1, out, E, G);
    fin_kernel<<<1, 64>>>(g3, be3, Einv);

    // final BN affine in place on d_out
    affine_kernel<<<4096, 256>>>(out, E * 16);
}

// round 11
// speedup vs baseline: 2.6307x; 2.6307x over previous
#include <cuda_runtime.h>

#define BN_EPS 1e-5f
#define MAX_E 1000000

// ---- device scratch (allocation-free: __device__ globals) ----
static __device__ float g_h[(size_t)MAX_E * 64];   // h1 / h2 scratch [E,64]
static __device__ float g_Wt1[64 * 256];           // W1 transposed [f][k]
static __device__ float g_Wt2[64 * 64];            // folded+transposed W2'
static __device__ float g_Wt3[64 * 64];            // folded+transposed W3'
static __device__ float g_bf2[64];
static __device__ float g_bf3[64];
static __device__ float g_sum[3][64];
static __device__ float g_sq[3][64];
static __device__ float g_s3[64];
static __device__ float g_t3[64];
static __device__ int   g_is64;                    // batch dtype flag (1 = int64)

// ---- packed fp32x2 FMA (Blackwell FFMA2) ----
__device__ __forceinline__ void ffma2(unsigned long long& d, unsigned long long a,
                                      unsigned long long b) {
    asm("fma.rn.f32x2 %0, %1, %2, %0;" : "+l"(d) : "l"(a), "l"(b));
}
__device__ __forceinline__ float2 unpack_f32x2(unsigned long long v) {
    float2 r;
    asm("mov.b64 {%0, %1}, %2;" : "=f"(r.x), "=f"(r.y) : "l"(v));
    return r;
}
__device__ __forceinline__ unsigned smem_u32(const void* p) {
    return (unsigned)__cvta_generic_to_shared(p);
}
__device__ __forceinline__ void cp16(unsigned dst, const void* src) {
    asm volatile("cp.async.cg.shared.global [%0], [%1], 16;" :: "r"(dst), "l"(src));
}
__device__ __forceinline__ void cp_commit() {
    asm volatile("cp.async.commit_group;" ::: "memory");
}
template <int N>
__device__ __forceinline__ void cp_wait() {
    asm volatile("cp.async.wait_group %0;" :: "n"(N) : "memory");
}

// ---- prep: zero stats, detect batch dtype, transpose W1 ----
__global__ void prep_kernel(const float* __restrict__ W1, const void* __restrict__ batch,
                            int E, int G) {
    if (blockIdx.x == 0) {
        float* s = &g_sum[0][0];
        float* q = &g_sq[0][0];
        for (int i = threadIdx.x; i < 192; i += blockDim.x) { s[i] = 0.f; q[i] = 0.f; }
        if (threadIdx.x == 0) {
            // int64 view of an int32 buffer packs two words -> values >= G
            // (except all-zero odd words, prob ~2^-640 over 64 samples).
            const long long* b64 = (const long long*)batch;
            int n = (E < 64) ? E : 64;
            int ok = 1;
            for (int i = 0; i < n; i++) {
                long long v = b64[i];
                if (v < 0 || v >= (long long)G) { ok = 0; break; }
            }
            g_is64 = ok;
        }
    }
    int tid = blockIdx.x * blockDim.x + threadIdx.x;
    for (int i = tid; i < 64 * 256; i += gridDim.x * blockDim.x) {
        int j = i >> 8, k = i & 255;
        g_Wt1[i] = W1[k * 64 + j];
    }
}

// ---- fold BN(layer LAYER) into next layer's weights ----
template <int LAYER>
__global__ void fold_kernel(const float* __restrict__ Wn, const float* __restrict__ bn,
                            const float* __restrict__ gamma, const float* __restrict__ beta,
                            float Einv) {
    __shared__ float s[64], t[64];
    int j = threadIdx.x;
    float mean = g_sum[LAYER][j] * Einv;
    float var  = g_sq[LAYER][j] * Einv - mean * mean;
    float sc = gamma[j] / sqrtf(var + BN_EPS);
    s[j] = sc;
    t[j] = beta[j] - mean * sc;
    __syncthreads();
    float* WtOut = (LAYER == 0) ? g_Wt2 : g_Wt3;
    float* bOut  = (LAYER == 0) ? g_bf2 : g_bf3;
    float bacc = bn[j];
#pragma unroll
    for (int k = 0; k < 64; k++) {
        float w = Wn[k * 64 + j];
        WtOut[j * 64 + k] = w * s[k];   // transposed + BN-scaled
        bacc += t[k] * w;
    }
    bOut[j] = bacc;
}

__global__ void fin_kernel(const float* __restrict__ gamma, const float* __restrict__ beta,
                           float Einv) {
    int j = threadIdx.x;
    float mean = g_sum[2][j] * Einv;
    float var  = g_sq[2][j] * Einv - mean * mean;
    float sc = gamma[j] / sqrtf(var + BN_EPS);
    g_s3[j] = sc;
    g_t3[j] = beta[j] - mean * sc;
}

__global__ void affine_kernel(float* __restrict__ out, int n4) {
    __shared__ float s[64], t[64];
    if (threadIdx.x < 64) { s[threadIdx.x] = g_s3[threadIdx.x]; t[threadIdx.x] = g_t3[threadIdx.x]; }
    __syncthreads();
    float4* o4 = reinterpret_cast<float4*>(out);
    for (int i = blockIdx.x * blockDim.x + threadIdx.x; i < n4; i += gridDim.x * blockDim.x) {
        float4 v = o4[i];
        int fb = (i & 15) << 2;
        v.x = v.x * s[fb] + t[fb];
        v.y = v.y * s[fb + 1] + t[fb + 1];
        v.z = v.z * s[fb + 2] + t[fb + 2];
        v.w = v.w * s[fb + 3] + t[fb + 3];
        o4[i] = v;
    }
}

// ---- stage one 64-k chunk of one 256-edge tile via cp.async ----
// Each thread stages row `tid` of the chunk (64 floats = 16 x 16B).
template <int LAYER>
__device__ __forceinline__ void stage_chunk(float* Adst, int t, int c,
                                            const float* in0, const float* in1,
                                            const float* in2, const float* ga,
                                            long long myB, int E, int tid) {
    int row = t * 256 + tid;
    if (row >= E) row = E - 1;        // duplicate tail row; epilogue guards stores
    if (row < 0) row = 0;
    const float4* g;
    if (LAYER == 0) {
        if (c == 3) {
            g = (const float4*)ga + (size_t)myB * 16;
        } else {
            const float* s = (c == 0) ? in0 : (c == 1) ? in1 : in2;
            g = (const float4*)s + (size_t)row * 16;
        }
    } else {
        g = (const float4*)g_h + (size_t)row * 16;
    }
    unsigned sa = smem_u32(Adst + tid * 68);
#pragma unroll
    for (int m = 0; m < 16; m++) cp16(sa + m * 16, g + m);
}

__device__ __forceinline__ long long load_batch_idx(const void* batch, int row, int G) {
    long long b = g_is64 ? ((const long long*)batch)[row]
                         : (long long)((const int*)batch)[row];
    if (b < 0) b = 0;
    if (b >= (long long)G) b = G - 1;
    return b;
}

// ---- persistent fused GEMM + relu + stats kernel ----
// 1 block/SM, 256 threads (8 warps). Tile = 256 edges x 64 f; thread tile 8x8.
// Warp layout: tx = lane&7 (f groups, f = tx+8j), ty = lane>>3 (edge groups,
// e = warp*32 + ty + 4i). K processed in 64-wide chunks, cp.async double-buffered.
// f32x2 lanes carry (even k, odd k) partial sums.
template <int NCH, int LAYER>
__global__ void __launch_bounds__(256, 1)
layer_kernel(const float* __restrict__ in0, const float* __restrict__ in1,
             const float* __restrict__ in2, const float* __restrict__ ga,
             const void* __restrict__ batch, const float* __restrict__ bias1,
             float* __restrict__ outParam, int E, int G) {
    constexpr int KDIM = NCH * 64;
    constexpr int WP = KDIM + 4;   // W pitch (floats): bank stride 4, 8B aligned
    constexpr int AP = 68;         // A pitch (floats)
    extern __shared__ float sm[];
    float* Ws   = sm;                    // [64][WP]
    float* Abuf = sm + 64 * WP;          // [2][256][AP]
    __shared__ float bs[64], ssum[64], ssq[64];

    const float* Wt   = (LAYER == 0) ? g_Wt1 : (LAYER == 1) ? g_Wt2 : g_Wt3;
    const float* bias = (LAYER == 0) ? bias1 : (LAYER == 1) ? g_bf2 : g_bf3;
    float* outp = (LAYER == 2) ? outParam : g_h;

    int tid = threadIdx.x;
    int warp = tid >> 5, lane = tid & 31, tx = lane & 7, ty = lane >> 3;

    // W -> smem once per block (float4-coalesced)
    {
        const float4* w4 = (const float4*)Wt;
        for (int i = tid; i < 64 * KDIM / 4; i += 256) {
            int j = i / (KDIM / 4), m = i - j * (KDIM / 4);
            *(float4*)&Ws[j * WP + m * 4] = w4[i];
        }
    }
    if (tid < 64) { bs[tid] = bias[tid]; ssum[tid] = 0.f; ssq[tid] = 0.f; }

    int nt = (E + 255) >> 8;
    int nb = gridDim.x;

    unsigned long long acc[8][8];
#pragma unroll
    for (int i = 0; i < 8; i++)
#pragma unroll
        for (int j = 0; j < 8; j++) acc[i][j] = 0ull;
    float ls[8], lq[8];
#pragma unroll
    for (int j = 0; j < 8; j++) { ls[j] = 0.f; lq[j] = 0.f; }

    int t0 = blockIdx.x;
    if (t0 < nt) {
        long long myB = 0;
        if (LAYER == 0) {
            int r = t0 * 256 + tid;
            if (r >= E) r = E - 1;
            myB = load_batch_idx(batch, r, G);
        }

        // prologue: stage (t0, chunk 0) into buffer 0
        stage_chunk<LAYER>(Abuf, t0, 0, in0, in1, in2, ga, myB, E, tid);
        cp_commit();

        int up = 0;  // buffer parity of current compute unit
        for (int t = t0; t < nt; t += nb) {
#pragma unroll 1
            for (int c = 0; c < NCH; c++) {
                int tn = (c + 1 < NCH) ? t : t + nb;
                int cn = (c + 1 < NCH) ? c + 1 : 0;
                bool hn = (tn < nt);
                if (hn) {
                    stage_chunk<LAYER>(Abuf + (up ^ 1) * 256 * AP, tn, cn,
                                       in0, in1, in2, ga, myB, E, tid);
                    cp_commit();
                    cp_wait<1>();
                } else {
                    cp_wait<0>();
                }
                __syncthreads();

                const float* Ab = Abuf + up * 256 * AP + (warp * 32 + ty) * AP;
                const float* Wb = Ws + tx * WP + c * 64;
#pragma unroll 4
                for (int kk = 0; kk < 64; kk += 2) {
                    unsigned long long av[8], wv[8];
#pragma unroll
                    for (int i = 0; i < 8; i++)
                        av[i] = *(const unsigned long long*)(Ab + i * 4 * AP + kk);
#pragma unroll
                    for (int j = 0; j < 8; j++)
                        wv[j] = *(const unsigned long long*)(Wb + j * 8 * WP + kk);
#pragma unroll
                    for (int i = 0; i < 8; i++)
#pragma unroll
                        for (int j = 0; j < 8; j++) ffma2(acc[i][j], av[i], wv[j]);
                }

                if (c == NCH - 1) {
                    int eb = t * 256 + warp * 32 + ty;
#pragma unroll
                    for (int i = 0; i < 8; i++) {
                        int ge = eb + 4 * i;
                        bool ok = ge < E;
#pragma unroll
                        for (int j = 0; j < 8; j++) {
                            float2 p = unpack_f32x2(acc[i][j]);
                            acc[i][j] = 0ull;
                            int f = tx + 8 * j;
                            float v = fmaxf(p.x + p.y + bs[f], 0.f);
                            if (ok) {
                                outp[(size_t)ge * 64 + f] = v;
                                ls[j] += v;
                                lq[j] += v * v;
                            }
                        }
                    }
                }
                __syncthreads();   // protect buf[up] before reuse as cp.async dst

                if (LAYER == 0 && hn && cn == 0) {  // next tile's gather indices
                    int r = tn * 256 + tid;
                    if (r >= E) r = E - 1;
                    myB = load_batch_idx(batch, r, G);
                }
                up ^= 1;
            }
        }
    }

    // stats: reduce over ty within warp (lanes differing in bits 3,4 share f)
#pragma unroll
    for (int j = 0; j < 8; j++) {
        ls[j] += __shfl_xor_sync(0xffffffffu, ls[j], 8);
        ls[j] += __shfl_xor_sync(0xffffffffu, ls[j], 16);
        lq[j] += __shfl_xor_sync(0xffffffffu, lq[j], 8);
        lq[j] += __shfl_xor_sync(0xffffffffu, lq[j], 16);
    }
    if (ty == 0) {
#pragma unroll
        for (int j = 0; j < 8; j++) {
            atomicAdd(&ssum[tx + 8 * j], ls[j]);
            atomicAdd(&ssq[tx + 8 * j], lq[j]);
        }
    }
    __syncthreads();
    if (tid < 64) {
        atomicAdd(&g_sum[LAYER][tid], ssum[tid]);
        atomicAdd(&g_sq[LAYER][tid], ssq[tid]);
    }
}

extern "C" void kernel_launch(void* const* d_in, const int* in_sizes, int n_in,
                              void* d_out, int out_size) {
    const float* src   = (const float*)d_in[0];
    const float* dst   = (const float*)d_in[1];
    const float* eat   = (const float*)d_in[2];
    const float* gat   = (const float*)d_in[3];
    const void*  batch = d_in[4];
    const float* W1 = (const float*)d_in[5];
    const float* b1 = (const float*)d_in[6];
    const float* W2 = (const float*)d_in[7];
    const float* b2 = (const float*)d_in[8];
    const float* W3 = (const float*)d_in[9];
    const float* b3 = (const float*)d_in[10];
    const float* g1 = (const float*)d_in[11];
    const float* be1 = (const float*)d_in[12];
    const float* g2 = (const float*)d_in[13];
    const float* be2 = (const float*)d_in[14];
    const float* g3 = (const float*)d_in[15];
    const float* be3 = (const float*)d_in[16];

    int E = in_sizes[0] / 64;
    int G = in_sizes[3] / 64;
    float Einv = 1.0f / (float)E;
    float* out = (float*)d_out;

    int nsm = 148;
    cudaDeviceGetAttribute(&nsm, cudaDevAttrMultiProcessorCount, 0);  // pure query, capture-safe
    if (nsm < 1) nsm = 148;
    int nt = (E + 255) >> 8;
    int nb = (nsm < nt) ? nsm : nt;
    if (nb < 1) nb = 1;

    constexpr int SM1 = (64 * 260 + 2 * 256 * 68) * 4;  // 205,824 B
    constexpr int SMN = (64 * 68 + 2 * 256 * 68) * 4;   // 156,672 B
    cudaFuncSetAttribute(layer_kernel<4, 0>, cudaFuncAttributeMaxDynamicSharedMemorySize, SM1);
    cudaFuncSetAttribute(layer_kernel<1, 1>, cudaFuncAttributeMaxDynamicSharedMemorySize, SMN);
    cudaFuncSetAttribute(layer_kernel<1, 2>, cudaFuncAttributeMaxDynamicSharedMemorySize, SMN);

    prep_kernel<<<16, 256>>>(W1, batch, E, G);

    // layer 1: concat(src,dest,edge,global[batch]) @ W1 + b1 -> relu -> g_h, stats[0]
    layer_kernel<4, 0><<<nb, 256, SM1>>>(src, dst, eat, gat, batch, b1, out, E, G);
    fold_kernel<0><<<1, 64>>>(W2, b2, g1, be1, Einv);

    // layer 2: g_h @ W2' + b2' -> relu -> g_h, stats[1]
    layer_kernel<1, 1><<<nb, 256, SMN>>>(src, dst, eat, gat, batch, b1, out, E, G);
    fold_kernel<1><<<1, 64>>>(W3, b3, g2, be2, Einv);

    // layer 3: g_h @ W3' + b3' -> relu -> d_out (pre-BN), stats[2]
    layer_kernel<1, 2><<<nb, 256, SMN>>>(src, dst, eat, gat, batch, b1, out, E, G);
    fin_kernel<<<1, 64>>>(g3, be3, Einv);

    // final BN affine in place on d_out
    affine_kernel<<<4096, 256>>>(out, E * 16);
}